// round 3
// baseline (speedup 1.0000x reference)
#include <cuda_runtime.h>

#define C    5
#define NPC  400
#define NN   (C*NPC)     // 2000
#define DF   64
#define HH   256
#define DOUT 64
#define EPC  12800
#define NE   (C*EPC)     // 64000
#define PAIRS 1999000LL

// ---------------- scratch (static, no allocation) ----------------
__device__ float g_deg[NN];
__device__ float g_dis[NN];
__device__ int   g_count[NN];
__device__ int   g_off[NN];
__device__ int   g_cursor[NN];
__device__ int   g_csr_row[NE];
__device__ float g_csr_norm[NE];
__device__ float g_XW1[NN*HH];
__device__ float g_H1[NN*HH];
__device__ float g_XW2[NN*DOUT];
__device__ float g_a[NN];
__device__ float g_b[NN];
__device__ float g_Ap[NN];
__device__ float g_Bp[NN];

// ---------------- init: deg=1 (self loop), counts=0 ----------------
__global__ void k_init() {
    int i = blockIdx.x * blockDim.x + threadIdx.x;
    if (i < NN) { g_deg[i] = 1.0f; g_count[i] = 0; }
}

// ---------------- degree + per-node edge counts (edge_index is int32!) ----------------
__global__ void k_deg(const int* __restrict__ ei, const float* __restrict__ ew) {
    int e = blockIdx.x * blockDim.x + threadIdx.x;
    if (e >= NE) return;
    int c = e / EPC, eo = e % EPC;
    int col = ei[c * 2 * EPC + EPC + eo];
    int g = c * NPC + col;
    atomicAdd(&g_deg[g], ew[e]);
    atomicAdd(&g_count[g], 1);
}

// ---------------- dis = rsqrt(deg); exclusive scan of counts ----------------
__global__ void k_scan() {
    __shared__ int sA[2048], sB[2048];
    int tid = threadIdx.x;                 // 1024 threads
    for (int i = tid; i < NN; i += 1024)
        g_dis[i] = rsqrtf(g_deg[i]);
    for (int k = 0; k < 2; k++) {
        int idx = tid + k * 1024;
        sA[idx] = (idx < NN) ? g_count[idx] : 0;
    }
    __syncthreads();
    int* src = sA; int* dst = sB;
    for (int d = 1; d < 2048; d <<= 1) {
        for (int k = 0; k < 2; k++) {
            int idx = tid + k * 1024;
            int v = src[idx];
            if (idx >= d) v += src[idx - d];
            dst[idx] = v;
        }
        __syncthreads();
        int* t = src; src = dst; dst = t;
    }
    for (int k = 0; k < 2; k++) {
        int idx = tid + k * 1024;
        if (idx < NN) {
            int off = src[idx] - g_count[idx];
            g_off[idx] = off;
            g_cursor[idx] = off;
        }
    }
}

// ---------------- fill CSR (row + norm) ----------------
__global__ void k_fill(const int* __restrict__ ei, const float* __restrict__ ew) {
    int e = blockIdx.x * blockDim.x + threadIdx.x;
    if (e >= NE) return;
    int c = e / EPC, eo = e % EPC;
    int row = ei[c * 2 * EPC + eo];
    int col = ei[c * 2 * EPC + EPC + eo];
    int g = c * NPC + col;
    float norm = g_dis[c * NPC + row] * ew[e] * g_dis[g];
    int p = atomicAdd(&g_cursor[g], 1);
    g_csr_row[p] = row;
    g_csr_norm[p] = norm;
}

// ---------------- XW1 = x @ W1  (per cluster, 8 nodes/block) ----------------
__global__ void k_gemm1(const float* __restrict__ x, const float* __restrict__ W1) {
    int c = blockIdx.y;
    int n0 = blockIdx.x * 8;
    int tid = threadIdx.x;          // 256
    __shared__ float sx[8][DF];
    for (int i = tid; i < 8 * DF; i += 256) {
        int m = i / DF, k = i % DF;
        sx[m][k] = x[(c * NPC + n0 + m) * DF + k];
    }
    __syncthreads();
    const float* Wc = W1 + c * DF * HH;
    int f = tid;
    float acc[8] = {0,0,0,0,0,0,0,0};
    #pragma unroll 4
    for (int k = 0; k < DF; k++) {
        float wv = Wc[k * HH + f];
        #pragma unroll
        for (int m = 0; m < 8; m++) acc[m] += sx[m][k] * wv;
    }
    #pragma unroll
    for (int m = 0; m < 8; m++)
        g_XW1[(c * NPC + n0 + m) * HH + f] = acc[m];
}

// ---------------- H1 = relu(Anorm @ XW1 + b1) ----------------
__global__ void k_gather1(const float* __restrict__ b1) {
    int g = blockIdx.x;             // node global id
    int c = g / NPC;
    int f = threadIdx.x;            // 256 = HH
    int start = g_off[g];
    int cnt = g_count[g];
    float dn = g_dis[g];
    float acc = dn * dn * g_XW1[g * HH + f];
    __shared__ int   sr[256];
    __shared__ float sn[256];
    int cbase = c * NPC;
    for (int base = 0; base < cnt; base += 256) {
        int m = cnt - base; if (m > 256) m = 256;
        if (f < m) {
            sr[f] = g_csr_row[start + base + f];
            sn[f] = g_csr_norm[start + base + f];
        }
        __syncthreads();
        for (int e = 0; e < m; e++)
            acc += sn[e] * g_XW1[(cbase + sr[e]) * HH + f];
        __syncthreads();
    }
    float v = acc + b1[c * HH + f];
    g_H1[g * HH + f] = fmaxf(v, 0.0f);
}

// ---------------- XW2 = H1 @ W2 (4 nodes/block) ----------------
__global__ void k_gemm2(const float* __restrict__ W2) {
    int c = blockIdx.y;
    int n0 = blockIdx.x * 4;
    int tid = threadIdx.x;          // 256
    int m = tid / DOUT, f = tid % DOUT;
    __shared__ float sh[4][HH];
    for (int i = tid; i < 4 * HH; i += 256) {
        int mm = i / HH, k = i % HH;
        sh[mm][k] = g_H1[(c * NPC + n0 + mm) * HH + k];
    }
    __syncthreads();
    const float* Wc = W2 + c * HH * DOUT;
    float acc = 0.0f;
    #pragma unroll 8
    for (int k = 0; k < HH; k++)
        acc += sh[m][k] * Wc[k * DOUT + f];
    g_XW2[(c * NPC + n0 + m) * DOUT + f] = acc;
}

// ---------------- H2 gather + attention dots a,b ----------------
__global__ void k_gather2(const float* __restrict__ b2, const float* __restrict__ Watt) {
    int g = blockIdx.x;
    int c = g / NPC;
    int f = threadIdx.x;            // 64
    int start = g_off[g];
    int cnt = g_count[g];
    float dn = g_dis[g];
    float acc = dn * dn * g_XW2[g * DOUT + f];
    __shared__ int   sr[64];
    __shared__ float sn[64];
    int cbase = c * NPC;
    for (int base = 0; base < cnt; base += 64) {
        int m = cnt - base; if (m > 64) m = 64;
        if (f < m) {
            sr[f] = g_csr_row[start + base + f];
            sn[f] = g_csr_norm[start + base + f];
        }
        __syncthreads();
        for (int e = 0; e < m; e++)
            acc += sn[e] * g_XW2[(cbase + sr[e]) * DOUT + f];
        __syncthreads();
    }
    float v = acc + b2[c * DOUT + f];
    float pa = v * Watt[f];
    float pb = v * Watt[DOUT + f];
    #pragma unroll
    for (int o = 16; o > 0; o >>= 1) {
        pa += __shfl_down_sync(0xffffffffu, pa, o);
        pb += __shfl_down_sync(0xffffffffu, pb, o);
    }
    __shared__ float ra[2], rb[2];
    int warp = f >> 5, lane = f & 31;
    if (lane == 0) { ra[warp] = pa; rb[warp] = pb; }
    __syncthreads();
    if (f == 0) {
        g_a[g] = ra[0] + ra[1];
        g_b[g] = rb[0] + rb[1];
    }
}

// ---------------- analytic mean/std over all pairs ----------------
__global__ void k_stats(const float* __restrict__ batt) {
    __shared__ double sA[2048], sB[2048];
    int tid = threadIdx.x;          // 1024
    double cc = (double)batt[0];
    for (int k = 0; k < 2; k++) {
        int idx = tid + k * 1024;
        sA[idx] = (idx < NN) ? ((double)g_a[idx] + cc) : 0.0;
    }
    __syncthreads();
    double* src = sA; double* dst = sB;
    for (int d = 1; d < 2048; d <<= 1) {
        for (int k = 0; k < 2; k++) {
            int idx = tid + k * 1024;
            double v = src[idx];
            if (idx >= d) v += src[idx - d];
            dst[idx] = v;
        }
        __syncthreads();
        double* t = src; src = dst; dst = t;
    }
    double psum = 0.0, psq = 0.0;
    for (int k = 0; k < 2; k++) {
        int idx = tid + k * 1024;
        if (idx < NN) {
            double ap = (double)g_a[idx] + cc;
            double bb = (double)g_b[idx];
            double prefA = src[idx] - ap;      // exclusive prefix sum of a'
            double w1 = (double)(NN - 1 - idx);
            double w2 = (double)idx;
            psum += w1 * ap + w2 * bb;
            psq  += w1 * ap * ap + w2 * bb * bb + 2.0 * bb * prefA;
        }
    }
    __syncthreads();
    sA[tid] = psum; sB[tid] = psq;
    __syncthreads();
    for (int s = 512; s > 0; s >>= 1) {
        if (tid < s) { sA[tid] += sA[tid + s]; sB[tid] += sB[tid + s]; }
        __syncthreads();
    }
    __shared__ double mS, invsS;
    if (tid == 0) {
        double sum = sA[0];
        double m = sum / (double)PAIRS;
        double var = (sB[0] - (double)PAIRS * m * m) / (double)(PAIRS - 1);
        mS = m;
        invsS = 1.0 / sqrt(var);
    }
    __syncthreads();
    double m = mS, invs = invsS;
    for (int k = 0; k < 2; k++) {
        int idx = tid + k * 1024;
        if (idx < NN) {
            g_Ap[idx] = (float)(((double)g_a[idx] + cc - m) * invs);
            g_Bp[idx] = (float)((double)g_b[idx] * invs);
        }
    }
}

// ---------------- output: sigmoid over all pairs, row-per-block ----------------
__global__ void k_out(float* __restrict__ out) {
    int i = blockIdx.x;             // 0..NN-1
    int cnt = NN - 1 - i;
    if (cnt <= 0) return;
    long long base = (long long)i * (NN - 1) - (long long)i * (i - 1) / 2;
    float Ai = g_Ap[i];
    for (int t = threadIdx.x; t < cnt; t += blockDim.x) {
        float z = Ai + g_Bp[i + 1 + t];
        out[base + t] = 1.0f / (1.0f + __expf(-z));
    }
}

// ---------------- launch ----------------
extern "C" void kernel_launch(void* const* d_in, const int* in_sizes, int n_in,
                              void* d_out, int out_size) {
    const float* x    = (const float*)d_in[0];
    const float* ew   = (const float*)d_in[1];
    const float* W1   = (const float*)d_in[2];
    const float* b1   = (const float*)d_in[3];
    const float* W2   = (const float*)d_in[4];
    const float* b2   = (const float*)d_in[5];
    const float* Watt = (const float*)d_in[6];
    const float* batt = (const float*)d_in[7];
    const int*   ei   = (const int*)d_in[8];
    float* out = (float*)d_out;

    k_init<<<(NN + 255) / 256, 256>>>();
    k_deg<<<(NE + 255) / 256, 256>>>(ei, ew);
    k_scan<<<1, 1024>>>();
    k_fill<<<(NE + 255) / 256, 256>>>(ei, ew);
    k_gemm1<<<dim3(NPC / 8, C), 256>>>(x, W1);
    k_gather1<<<NN, 256>>>(b1);
    k_gemm2<<<dim3(NPC / 4, C), 256>>>(W2);
    k_gather2<<<NN, 64>>>(b2, Watt);
    k_stats<<<1, 1024>>>(batt);
    k_out<<<NN, 256>>>(out);
}

// round 6
// speedup vs baseline: 1.1733x; 1.1733x over previous
#include <cuda_runtime.h>

#define C    5
#define NPC  400
#define NN   (C*NPC)     // 2000
#define DF   64
#define HH   256
#define DOUT 64
#define EPC  12800
#define NE   (C*EPC)     // 64000
#define PAIRS 1999000LL
#define CAP  128

// ---------------- scratch (static, no allocation) ----------------
__device__ unsigned long long g_bucket[NN*CAP];   // {row, w} packed
__device__ int   g_count[NN];     // zeroed by K4 of previous invocation (zero at load)
__device__ float g_degsum[NN];    // ditto
__device__ float g_XW1[NN*HH];
__device__ float g_XW2[NN*DOUT];
__device__ float g_a[NN];
__device__ float g_b[NN];
__device__ float g_Ea[NN];        // exp(-Ap)
__device__ float g_Fb[NN];        // exp(-Bp)

// ================= K1: edge bucketing (blocks 0..124) + gemm1 (blocks 125..374) =================
__global__ void k1(const int* __restrict__ ei, const float* __restrict__ ew,
                   const float* __restrict__ x, const float* __restrict__ W1) {
    int bid = blockIdx.x, tid = threadIdx.x;
    if (bid < 125) {
        // 512 edges per block, 2 per thread; 25 blocks per cluster (512*25 = 12800)
        int c = bid / 25;
        int eo = (bid % 25) * 512 + tid;
        const int* base = ei + c * 2 * EPC;
        const float* ewc = ew + c * EPC;
        #pragma unroll
        for (int k = 0; k < 2; k++) {
            int e = eo + k * 256;
            int row = base[e];
            int col = base[EPC + e];
            float w = ewc[e];
            int g = c * NPC + col;
            atomicAdd(&g_degsum[g], w);
            int slot = atomicAdd(&g_count[g], 1);
            if (slot < CAP)
                g_bucket[g * CAP + slot] =
                    ((unsigned long long)(unsigned)row << 32) |
                    (unsigned long long)__float_as_uint(w);
        }
    } else {
        // gemm1: XW1 = x @ W1, 8 nodes/block, 50 blocks/cluster
        int b = bid - 125;                 // 0..249
        int c = b / 50, n0l = (b % 50) * 8;
        __shared__ float sx[8][DF];
        const float* xc = x + (c * NPC + n0l) * DF;
        for (int i = tid; i < 8 * DF; i += 256)
            sx[i / DF][i % DF] = xc[i];
        __syncthreads();
        const float* Wc = W1 + c * DF * HH;
        float acc[8] = {0,0,0,0,0,0,0,0};
        #pragma unroll 4
        for (int k = 0; k < DF; k++) {
            float wv = Wc[k * HH + tid];
            #pragma unroll
            for (int m = 0; m < 8; m++) acc[m] += sx[m][k] * wv;
        }
        #pragma unroll
        for (int m = 0; m < 8; m++)
            g_XW1[(c * NPC + n0l + m) * HH + tid] = acc[m];
    }
}

// ================= K2: gather1 + b1 + relu + gemm2 (4 nodes/block, 500 blocks, 256 thr) =========
__global__ void k2(const float* __restrict__ b1, const float* __restrict__ W2) {
    int n0 = blockIdx.x * 4;
    int c = n0 / NPC, cbase = c * NPC;
    int tid = threadIdx.x;

    __shared__ int   scnt[4];
    __shared__ float sdn[4];
    __shared__ int   ssr[4 * CAP];
    __shared__ float ssn[4 * CAP];
    __shared__ float sh[4][HH];
    __shared__ float sred[4 * 4 * 64];

    if (tid < 4) {
        int cnt = g_count[n0 + tid]; if (cnt > CAP) cnt = CAP;
        scnt[tid] = cnt;
        sdn[tid] = rsqrtf(1.0f + g_degsum[n0 + tid]);
    }
    __syncthreads();

    for (int idx = tid; idx < 4 * CAP; idx += 256) {
        int m = idx >> 7, s = idx & (CAP - 1);
        if (s < scnt[m]) {
            unsigned long long pk = g_bucket[(n0 + m) * CAP + s];
            int row = (int)(pk >> 32);
            float w = __uint_as_float((unsigned)pk);
            ssr[idx] = row;
            ssn[idx] = rsqrtf(1.0f + g_degsum[cbase + row]) * w * sdn[m];
        }
    }
    __syncthreads();

    float bb = b1[c * HH + tid];
    for (int m = 0; m < 4; m++) {
        float dn = sdn[m];
        float acc = dn * dn * g_XW1[(n0 + m) * HH + tid];
        int cnt = scnt[m];
        const int* pr = ssr + m * CAP;
        const float* pn = ssn + m * CAP;
        #pragma unroll 4
        for (int e = 0; e < cnt; e++)
            acc += pn[e] * g_XW1[(cbase + pr[e]) * HH + tid];
        sh[m][tid] = fmaxf(acc + bb, 0.0f);
    }
    __syncthreads();

    // gemm2: each thread = (k-quarter q, output f); W2 read once per block
    int q = tid >> 6, f = tid & 63;
    const float* Wc = W2 + c * HH * DOUT + q * 64 * DOUT;
    float p0 = 0, p1 = 0, p2 = 0, p3 = 0;
    #pragma unroll 8
    for (int kk = 0; kk < 64; kk++) {
        int k = q * 64 + kk;
        float wv = Wc[kk * DOUT + f];
        p0 += sh[0][k] * wv; p1 += sh[1][k] * wv;
        p2 += sh[2][k] * wv; p3 += sh[3][k] * wv;
    }
    sred[q * 256 + 0 * 64 + f] = p0;
    sred[q * 256 + 1 * 64 + f] = p1;
    sred[q * 256 + 2 * 64 + f] = p2;
    sred[q * 256 + 3 * 64 + f] = p3;
    __syncthreads();

    int m = tid >> 6;   // f unchanged
    float v = sred[0 * 256 + m * 64 + f] + sred[1 * 256 + m * 64 + f]
            + sred[2 * 256 + m * 64 + f] + sred[3 * 256 + m * 64 + f];
    // NOTE: b2 is added post-aggregation, in K3 (matches reference)
    g_XW2[(n0 + m) * DOUT + f] = v;
}

// ================= K3: gather2 + b2 + attention dots (2000 blocks, 128 thr) =====================
__global__ void k3(const float* __restrict__ b2, const float* __restrict__ Watt) {
    int g = blockIdx.x;
    int c = g / NPC, cbase = c * NPC;
    int tid = threadIdx.x;   // 128

    __shared__ int   sr[CAP];
    __shared__ float sn[CAP];
    __shared__ float sacc[128];
    __shared__ float ra[2], rb[2];

    int cnt = g_count[g]; if (cnt > CAP) cnt = CAP;
    float dn = rsqrtf(1.0f + g_degsum[g]);
    if (tid < cnt) {
        unsigned long long pk = g_bucket[g * CAP + tid];
        int row = (int)(pk >> 32);
        float w = __uint_as_float((unsigned)pk);
        sr[tid] = row;
        sn[tid] = rsqrtf(1.0f + g_degsum[cbase + row]) * w * dn;
    }
    __syncthreads();

    int q = tid >> 6, f = tid & 63;
    float acc = (q == 0) ? dn * dn * g_XW2[g * DOUT + f] : 0.0f;
    for (int e = q; e < cnt; e += 2)
        acc += sn[e] * g_XW2[(cbase + sr[e]) * DOUT + f];
    sacc[tid] = acc;
    __syncthreads();

    if (tid < 64) {
        float v = sacc[tid] + sacc[tid + 64] + b2[c * DOUT + tid];
        float pa = v * Watt[tid];
        float pb = v * Watt[DOUT + tid];
        #pragma unroll
        for (int o = 16; o > 0; o >>= 1) {
            pa += __shfl_down_sync(0xffffffffu, pa, o);
            pb += __shfl_down_sync(0xffffffffu, pb, o);
        }
        if ((tid & 31) == 0) { ra[tid >> 5] = pa; rb[tid >> 5] = pb; }
    }
    __syncthreads();
    if (tid == 0) {
        g_a[g] = ra[0] + ra[1];
        g_b[g] = rb[0] + rb[1];
    }
}

// ================= K4: analytic pair mean/std + exp precompute + scratch re-zero ================
__global__ void k4(const float* __restrict__ batt) {
    __shared__ double sA[2048], sB[2048];
    int tid = threadIdx.x;          // 1024
    double cc = (double)batt[0];
    for (int k = 0; k < 2; k++) {
        int idx = tid + k * 1024;
        sA[idx] = (idx < NN) ? ((double)g_a[idx] + cc) : 0.0;
    }
    __syncthreads();
    double* src = sA; double* dst = sB;
    for (int d = 1; d < 2048; d <<= 1) {
        for (int k = 0; k < 2; k++) {
            int idx = tid + k * 1024;
            double v = src[idx];
            if (idx >= d) v += src[idx - d];
            dst[idx] = v;
        }
        __syncthreads();
        double* t = src; src = dst; dst = t;
    }
    // src = inclusive prefix of a'
    __shared__ double totA_s;
    if (tid == 0) totA_s = src[NN - 1];

    double psum = 0.0, psq = 0.0;
    for (int k = 0; k < 2; k++) {
        int idx = tid + k * 1024;
        if (idx < NN) {
            double ap = (double)g_a[idx] + cc;
            double bb = (double)g_b[idx];
            double prefA = src[idx] - ap;      // exclusive prefix
            double w1 = (double)(NN - 1 - idx);
            double w2 = (double)idx;
            psum += w1 * ap + w2 * bb;
            psq  += w1 * ap * ap + w2 * bb * bb + 2.0 * bb * prefA;
        }
    }
    __syncthreads();
    sA[tid] = psum; sB[tid] = psq;
    __syncthreads();
    for (int s = 512; s > 0; s >>= 1) {
        if (tid < s) { sA[tid] += sA[tid + s]; sB[tid] += sB[tid + s]; }
        __syncthreads();
    }
    __shared__ double mS, invsS;
    if (tid == 0) {
        double sum = sA[0];
        double m = sum / (double)PAIRS;
        double var = (sB[0] - (double)PAIRS * m * m) / (double)(PAIRS - 1);
        mS = m;
        invsS = 1.0 / sqrt(var);
    }
    __syncthreads();
    double m = mS, invs = invsS;
    double mA = totA_s / (double)NN;    // split mean so Ap, Bp both stay centered
    double mB = m - mA;
    for (int k = 0; k < 2; k++) {
        int idx = tid + k * 1024;
        if (idx < NN) {
            float Ap = (float)(((double)g_a[idx] + cc - mA) * invs);
            float Bp = (float)(((double)g_b[idx] - mB) * invs);
            g_Ea[idx] = __expf(-Ap);
            g_Fb[idx] = __expf(-Bp);
            g_count[idx]  = 0;      // re-zero scratch for the next graph replay
            g_degsum[idx] = 0.0f;
        }
    }
}

// ================= K5: sigmoid over all pairs (row-paired for balance, float4 stores) ===========
__global__ void k5(float* __restrict__ out) {
    int bid = blockIdx.x;           // 0..999
    #pragma unroll 1
    for (int r = 0; r < 2; r++) {
        int i = (r == 0) ? bid : 1998 - bid;
        if (r == 1 && i == bid) break;        // bid==999 handled once
        int cnt = NN - 1 - i;
        long long base = (long long)i * (NN - 1) - (long long)i * (i - 1) / 2;
        float Ai = g_Ea[i];
        const float* F = g_Fb + i + 1;
        float* o = out + base;

        int head = (int)((4 - (base & 3)) & 3);
        if (head > cnt) head = cnt;
        if (threadIdx.x < head) {
            float e = Ai * F[threadIdx.x];
            o[threadIdx.x] = __fdividef(1.0f, 1.0f + e);
        }
        int rem = cnt - head;
        int nv = rem >> 2;
        for (int v = threadIdx.x; v < nv; v += blockDim.x) {
            int idx = head + v * 4;
            float e0 = Ai * F[idx];
            float e1 = Ai * F[idx + 1];
            float e2 = Ai * F[idx + 2];
            float e3 = Ai * F[idx + 3];
            float4 r4;
            r4.x = __fdividef(1.0f, 1.0f + e0);
            r4.y = __fdividef(1.0f, 1.0f + e1);
            r4.z = __fdividef(1.0f, 1.0f + e2);
            r4.w = __fdividef(1.0f, 1.0f + e3);
            *(float4*)(o + idx) = r4;
        }
        int tb = head + nv * 4;
        int t = tb + (int)threadIdx.x;
        if (t < cnt) {
            float e = Ai * F[t];
            o[t] = __fdividef(1.0f, 1.0f + e);
        }
    }
}

// ---------------- launch ----------------
extern "C" void kernel_launch(void* const* d_in, const int* in_sizes, int n_in,
                              void* d_out, int out_size) {
    const float* x    = (const float*)d_in[0];
    const float* ew   = (const float*)d_in[1];
    const float* W1   = (const float*)d_in[2];
    const float* b1   = (const float*)d_in[3];
    const float* W2   = (const float*)d_in[4];
    const float* b2   = (const float*)d_in[5];
    const float* Watt = (const float*)d_in[6];
    const float* batt = (const float*)d_in[7];
    const int*   ei   = (const int*)d_in[8];
    float* out = (float*)d_out;

    k1<<<375, 256>>>(ei, ew, x, W1);
    k2<<<500, 256>>>(b1, W2);
    k3<<<NN, 128>>>(b2, Watt);
    k4<<<1, 1024>>>(batt);
    k5<<<1000, 256>>>(out);
}

// round 7
// speedup vs baseline: 1.7801x; 1.5171x over previous
#include <cuda_runtime.h>

#define C    5
#define NPC  400
#define NN   (C*NPC)     // 2000
#define DF   64
#define HH   256
#define DOUT 64
#define EPC  12800
#define NE   (C*EPC)     // 64000
#define PAIRS 1999000LL
#define CAP  128

// ---------------- scratch (static, no allocation) ----------------
__device__ unsigned long long g_bucket[NN*CAP];   // {row, w} packed
__device__ int   g_count[NN];     // zeroed by K4 of previous invocation (zero at load)
__device__ float g_degsum[NN];    // ditto
__device__ float g_XW1[NN*HH];
__device__ float g_XW2[NN*DOUT];
__device__ float g_a[NN];
__device__ float g_b[NN];
__device__ float g_Ea[NN];        // exp(-(alpha*invs - off))
__device__ float g_Fb[NN];        // exp(-(beta *invs - off))

// ================= K1: edge bucketing (blocks 0..124) + gemm1 (blocks 125..374) =================
__global__ void k1(const int* __restrict__ ei, const float* __restrict__ ew,
                   const float* __restrict__ x, const float* __restrict__ W1) {
    int bid = blockIdx.x, tid = threadIdx.x;
    if (bid < 125) {
        int c = bid / 25;
        int eo = (bid % 25) * 512 + tid;
        const int* base = ei + c * 2 * EPC;
        const float* ewc = ew + c * EPC;
        #pragma unroll
        for (int k = 0; k < 2; k++) {
            int e = eo + k * 256;
            int row = base[e];
            int col = base[EPC + e];
            float w = ewc[e];
            int g = c * NPC + col;
            atomicAdd(&g_degsum[g], w);
            int slot = atomicAdd(&g_count[g], 1);
            if (slot < CAP)
                g_bucket[g * CAP + slot] =
                    ((unsigned long long)(unsigned)row << 32) |
                    (unsigned long long)__float_as_uint(w);
        }
    } else {
        int b = bid - 125;                 // 0..249
        int c = b / 50, n0l = (b % 50) * 8;
        __shared__ float sx[8][DF];
        const float* xc = x + (c * NPC + n0l) * DF;
        for (int i = tid; i < 8 * DF; i += 256)
            sx[i / DF][i % DF] = xc[i];
        __syncthreads();
        const float* Wc = W1 + c * DF * HH;
        float acc[8] = {0,0,0,0,0,0,0,0};
        #pragma unroll 4
        for (int k = 0; k < DF; k++) {
            float wv = Wc[k * HH + tid];
            #pragma unroll
            for (int m = 0; m < 8; m++) acc[m] += sx[m][k] * wv;
        }
        #pragma unroll
        for (int m = 0; m < 8; m++)
            g_XW1[(c * NPC + n0l + m) * HH + tid] = acc[m];
    }
}

// ================= K2: gather1 + b1 + relu + gemm2 (4 nodes/block, 500 blocks, 256 thr) =========
__global__ void k2(const float* __restrict__ b1, const float* __restrict__ W2) {
    int n0 = blockIdx.x * 4;
    int c = n0 / NPC, cbase = c * NPC;
    int tid = threadIdx.x;

    __shared__ int   scnt[4];
    __shared__ float sdn[4];
    __shared__ int   ssr[4 * CAP];
    __shared__ float ssn[4 * CAP];
    __shared__ float sh[4][HH];
    __shared__ float sred[4 * 4 * 64];

    if (tid < 4) {
        int cnt = g_count[n0 + tid]; if (cnt > CAP) cnt = CAP;
        scnt[tid] = cnt;
        sdn[tid] = rsqrtf(1.0f + g_degsum[n0 + tid]);
    }
    __syncthreads();

    for (int idx = tid; idx < 4 * CAP; idx += 256) {
        int m = idx >> 7, s = idx & (CAP - 1);
        if (s < scnt[m]) {
            unsigned long long pk = g_bucket[(n0 + m) * CAP + s];
            int row = (int)(pk >> 32);
            float w = __uint_as_float((unsigned)pk);
            ssr[idx] = row;
            ssn[idx] = rsqrtf(1.0f + g_degsum[cbase + row]) * w * sdn[m];
        }
    }
    __syncthreads();

    float bb = b1[c * HH + tid];
    for (int m = 0; m < 4; m++) {
        float dn = sdn[m];
        float acc = dn * dn * g_XW1[(n0 + m) * HH + tid];
        int cnt = scnt[m];
        const int* pr = ssr + m * CAP;
        const float* pn = ssn + m * CAP;
        #pragma unroll 4
        for (int e = 0; e < cnt; e++)
            acc += pn[e] * g_XW1[(cbase + pr[e]) * HH + tid];
        sh[m][tid] = fmaxf(acc + bb, 0.0f);
    }
    __syncthreads();

    int q = tid >> 6, f = tid & 63;
    const float* Wc = W2 + c * HH * DOUT + q * 64 * DOUT;
    float p0 = 0, p1 = 0, p2 = 0, p3 = 0;
    #pragma unroll 8
    for (int kk = 0; kk < 64; kk++) {
        int k = q * 64 + kk;
        float wv = Wc[kk * DOUT + f];
        p0 += sh[0][k] * wv; p1 += sh[1][k] * wv;
        p2 += sh[2][k] * wv; p3 += sh[3][k] * wv;
    }
    sred[q * 256 + 0 * 64 + f] = p0;
    sred[q * 256 + 1 * 64 + f] = p1;
    sred[q * 256 + 2 * 64 + f] = p2;
    sred[q * 256 + 3 * 64 + f] = p3;
    __syncthreads();

    int m = tid >> 6;
    float v = sred[0 * 256 + m * 64 + f] + sred[1 * 256 + m * 64 + f]
            + sred[2 * 256 + m * 64 + f] + sred[3 * 256 + m * 64 + f];
    g_XW2[(n0 + m) * DOUT + f] = v;
}

// ================= K3: gather2 + b2 + attention dots (2000 blocks, 128 thr) =====================
__global__ void k3(const float* __restrict__ b2, const float* __restrict__ Watt) {
    int g = blockIdx.x;
    int c = g / NPC, cbase = c * NPC;
    int tid = threadIdx.x;   // 128

    __shared__ int   sr[CAP];
    __shared__ float sn[CAP];
    __shared__ float sacc[128];
    __shared__ float ra[2], rb[2];

    int cnt = g_count[g]; if (cnt > CAP) cnt = CAP;
    float dn = rsqrtf(1.0f + g_degsum[g]);
    if (tid < cnt) {
        unsigned long long pk = g_bucket[g * CAP + tid];
        int row = (int)(pk >> 32);
        float w = __uint_as_float((unsigned)pk);
        sr[tid] = row;
        sn[tid] = rsqrtf(1.0f + g_degsum[cbase + row]) * w * dn;
    }
    __syncthreads();

    int q = tid >> 6, f = tid & 63;
    float acc = (q == 0) ? dn * dn * g_XW2[g * DOUT + f] : 0.0f;
    for (int e = q; e < cnt; e += 2)
        acc += sn[e] * g_XW2[(cbase + sr[e]) * DOUT + f];
    sacc[tid] = acc;
    __syncthreads();

    if (tid < 64) {
        float v = sacc[tid] + sacc[tid + 64] + b2[c * DOUT + tid];
        float pa = v * Watt[tid];
        float pb = v * Watt[DOUT + tid];
        #pragma unroll
        for (int o = 16; o > 0; o >>= 1) {
            pa += __shfl_down_sync(0xffffffffu, pa, o);
            pb += __shfl_down_sync(0xffffffffu, pb, o);
        }
        if ((tid & 31) == 0) { ra[tid >> 5] = pa; rb[tid >> 5] = pb; }
    }
    __syncthreads();
    if (tid == 0) {
        g_a[g] = ra[0] + ra[1];
        g_b[g] = rb[0] + rb[1];
    }
}

// ================= K4: analytic pair mean/std, fp32 shfl scan, FP64 only at the tip =============
// logits z_ij = a'_i + b_j (i<j), a' = a + b_att.
// Center: alpha = a' - mA, beta = b - mB  (statistic is shift-invariant, so fp32
// rounding of mA/mB cancels exactly in (alpha+beta-mu)).
// mu  = [ Sum_i (N-1-i) alpha_i + Sum_j j beta_j ] / P
// Var = ( Q + 2X - P mu^2 ) / (P-1),  Q = Sum (N-1-i) alpha^2 + Sum j beta^2,
// X = Sum_j beta_j * exclusive_prefix_alpha(j)
__global__ void k4(const float* __restrict__ batt) {
    const int tid = threadIdx.x;            // 1024
    const int lane = tid & 31, warp = tid >> 5;   // 32 warps
    __shared__ double s_redA[32], s_redB[32];
    __shared__ float  s_scan[32];
    __shared__ double s_red3[96];
    __shared__ double s_mAB[2];
    __shared__ double s_out[2];

    float cc = batt[0];
    int e0 = tid * 2, e1 = tid * 2 + 1;
    bool v0 = e0 < NN, v1 = e1 < NN;
    float a0 = v0 ? g_a[e0] + cc : 0.0f;
    float a1 = v1 ? g_a[e1] + cc : 0.0f;
    float b0 = v0 ? g_b[e0] : 0.0f;
    float b1v = v1 ? g_b[e1] : 0.0f;

    // ---- means ----
    float sa = a0 + a1, sb = b0 + b1v;
    #pragma unroll
    for (int o = 16; o > 0; o >>= 1) {
        sa += __shfl_down_sync(0xffffffffu, sa, o);
        sb += __shfl_down_sync(0xffffffffu, sb, o);
    }
    if (lane == 0) { s_redA[warp] = (double)sa; s_redB[warp] = (double)sb; }
    __syncthreads();
    if (warp == 0) {
        double da = s_redA[lane], db = s_redB[lane];
        #pragma unroll
        for (int o = 16; o > 0; o >>= 1) {
            da += __shfl_down_sync(0xffffffffu, da, o);
            db += __shfl_down_sync(0xffffffffu, db, o);
        }
        if (lane == 0) { s_mAB[0] = da / (double)NN; s_mAB[1] = db / (double)NN; }
    }
    __syncthreads();
    float mA = (float)s_mAB[0], mB = (float)s_mAB[1];
    float al0 = v0 ? a0 - mA : 0.0f;
    float al1 = v1 ? a1 - mA : 0.0f;
    float be0 = v0 ? b0 - mB : 0.0f;
    float be1 = v1 ? b1v - mB : 0.0f;

    // ---- hierarchical exclusive scan of alpha ----
    float ls = al0 + al1;
    float inc = ls;
    #pragma unroll
    for (int o = 1; o < 32; o <<= 1) {
        float t = __shfl_up_sync(0xffffffffu, inc, o);
        if (lane >= o) inc += t;
    }
    if (lane == 31) s_scan[warp] = inc;
    __syncthreads();
    if (warp == 0) {
        float wsum = s_scan[lane];
        float wi = wsum;
        #pragma unroll
        for (int o = 1; o < 32; o <<= 1) {
            float t = __shfl_up_sync(0xffffffffu, wi, o);
            if (lane >= o) wi += t;
        }
        s_scan[lane] = wi - wsum;   // exclusive warp offsets
    }
    __syncthreads();
    float pref0 = s_scan[warp] + (inc - ls);   // exclusive prefix at e0
    float pref1 = pref0 + al0;

    // ---- weighted sums ----
    float w0 = (float)(NN - 1 - e0), w1 = (float)(NN - 1 - e1);
    float j0 = (float)e0, j1 = (float)e1;
    float W = w0 * al0 + j0 * be0 + w1 * al1 + j1 * be1;
    float Q = w0 * al0 * al0 + j0 * be0 * be0 + w1 * al1 * al1 + j1 * be1 * be1;
    float X = be0 * pref0 + be1 * pref1;
    #pragma unroll
    for (int o = 16; o > 0; o >>= 1) {
        W += __shfl_down_sync(0xffffffffu, W, o);
        Q += __shfl_down_sync(0xffffffffu, Q, o);
        X += __shfl_down_sync(0xffffffffu, X, o);
    }
    if (lane == 0) { s_red3[warp] = (double)W; s_red3[32 + warp] = (double)Q; s_red3[64 + warp] = (double)X; }
    __syncthreads();
    if (warp == 0) {
        double dW = s_red3[lane], dQ = s_red3[32 + lane], dX = s_red3[64 + lane];
        #pragma unroll
        for (int o = 16; o > 0; o >>= 1) {
            dW += __shfl_down_sync(0xffffffffu, dW, o);
            dQ += __shfl_down_sync(0xffffffffu, dQ, o);
            dX += __shfl_down_sync(0xffffffffu, dX, o);
        }
        if (lane == 0) {
            double mu = dW / (double)PAIRS;
            double Qt = dQ + 2.0 * dX;
            double var = (Qt - (double)PAIRS * mu * mu) / (double)(PAIRS - 1);
            double invs = 1.0 / sqrt(var);
            s_out[0] = invs;
            s_out[1] = 0.5 * mu * invs;
        }
    }
    __syncthreads();
    float invs = (float)s_out[0], off = (float)s_out[1];
    // Ea[i]*Fb[j] = exp(-(alpha_i+beta_j-mu)*invs) = exp(-(z-m)/s)
    if (v0) {
        g_Ea[e0] = __expf(off - al0 * invs);
        g_Fb[e0] = __expf(off - be0 * invs);
        g_count[e0] = 0; g_degsum[e0] = 0.0f;
    }
    if (v1) {
        g_Ea[e1] = __expf(off - al1 * invs);
        g_Fb[e1] = __expf(off - be1 * invs);
        g_count[e1] = 0; g_degsum[e1] = 0.0f;
    }
}

// ================= K5: sigmoid over all pairs (row-paired for balance, float4 stores) ===========
__global__ void k5(float* __restrict__ out) {
    int bid = blockIdx.x;           // 0..999
    #pragma unroll 1
    for (int r = 0; r < 2; r++) {
        int i = (r == 0) ? bid : 1998 - bid;
        if (r == 1 && i == bid) break;
        int cnt = NN - 1 - i;
        long long base = (long long)i * (NN - 1) - (long long)i * (i - 1) / 2;
        float Ai = g_Ea[i];
        const float* F = g_Fb + i + 1;
        float* o = out + base;

        int head = (int)((4 - (base & 3)) & 3);
        if (head > cnt) head = cnt;
        if (threadIdx.x < head) {
            float e = Ai * F[threadIdx.x];
            o[threadIdx.x] = __fdividef(1.0f, 1.0f + e);
        }
        int rem = cnt - head;
        int nv = rem >> 2;
        for (int v = threadIdx.x; v < nv; v += blockDim.x) {
            int idx = head + v * 4;
            float e0 = Ai * F[idx];
            float e1 = Ai * F[idx + 1];
            float e2 = Ai * F[idx + 2];
            float e3 = Ai * F[idx + 3];
            float4 r4;
            r4.x = __fdividef(1.0f, 1.0f + e0);
            r4.y = __fdividef(1.0f, 1.0f + e1);
            r4.z = __fdividef(1.0f, 1.0f + e2);
            r4.w = __fdividef(1.0f, 1.0f + e3);
            *(float4*)(o + idx) = r4;
        }
        int tb = head + nv * 4;
        int t = tb + (int)threadIdx.x;
        if (t < cnt) {
            float e = Ai * F[t];
            o[t] = __fdividef(1.0f, 1.0f + e);
        }
    }
}

// ---------------- launch ----------------
extern "C" void kernel_launch(void* const* d_in, const int* in_sizes, int n_in,
                              void* d_out, int out_size) {
    const float* x    = (const float*)d_in[0];
    const float* ew   = (const float*)d_in[1];
    const float* W1   = (const float*)d_in[2];
    const float* b1   = (const float*)d_in[3];
    const float* W2   = (const float*)d_in[4];
    const float* b2   = (const float*)d_in[5];
    const float* Watt = (const float*)d_in[6];
    const float* batt = (const float*)d_in[7];
    const int*   ei   = (const int*)d_in[8];
    float* out = (float*)d_out;

    k1<<<375, 256>>>(ei, ew, x, W1);
    k2<<<500, 256>>>(b1, W2);
    k3<<<NN, 128>>>(b2, Watt);
    k4<<<1, 1024>>>(batt);
    k5<<<1000, 256>>>(out);
}